// round 5
// baseline (speedup 1.0000x reference)
#include <cuda_runtime.h>

// NCC2D: local normalized cross-correlation, 9x9 box, zero pad, scalar -mean(cc)
// Inputs: y_true, y_pred : [32,1,512,512] fp32. Output: 1 fp32.
//
// cross = IJ_sum - I_sum*J_sum/81 ; I_var = I2_sum - I_sum^2/81 (ditto J)
// cc = cross^2 / (I_var*J_var + 1e-5) ; out = -mean(cc)
//
// One warp spans a full 512-wide row strip (16 cols/lane); halos via shuffle.
// Steady-state loop is branchless with software-prefetched add-row (DRAM) and
// early-issued sub-row (L2) so FMA work covers memory latency.

#define IMG_W 512
#define IMG_H 512
#define NBATCH 32
#define STRIP 8
#define NSTRIPS (IMG_H / STRIP)      // 64
#define NTASK (NBATCH * NSTRIPS)     // 2048 warps
#define WPB 4
#define NBLOCKS (NTASK / WPB)        // 512
#define OUTC 16

__device__ float g_partials[NTASK];
__device__ unsigned int g_counter;

#define WW(A, L, R, i) ((i) < 4 ? (L)[(i)] : ((i) < 20 ? (A)[(i)-4] : (R)[(i)-20]))

struct Acc {
    float vI[OUTC], vJ[OUTC], vI2[OUTC], vJ2[OUTC], vIJ[OUTC];
};

__device__ __forceinline__ void load_rows(const float* __restrict__ Irow,
                                          const float* __restrict__ Jrow,
                                          float4 (&bi)[4], float4 (&bj)[4]) {
    const float4* pI = reinterpret_cast<const float4*>(Irow);
    const float4* pJ = reinterpret_cast<const float4*>(Jrow);
#pragma unroll
    for (int c = 0; c < 4; c++) { bi[c] = pI[c]; bj[c] = pJ[c]; }
}

template <bool ADD>
__device__ __forceinline__ void update(Acc& A, const float4 (&bi)[4],
                                       const float4 (&bj)[4]) {
#pragma unroll
    for (int c = 0; c < 4; c++) {
        float av[4] = {bi[c].x, bi[c].y, bi[c].z, bi[c].w};
        float cv[4] = {bj[c].x, bj[c].y, bj[c].z, bj[c].w};
#pragma unroll
        for (int q = 0; q < 4; q++) {
            int j = c * 4 + q;
            float a = av[q], cc = cv[q];
            if (ADD) {
                A.vI[j] += a; A.vJ[j] += cc;
                A.vI2[j] = fmaf(a, a, A.vI2[j]);
                A.vJ2[j] = fmaf(cc, cc, A.vJ2[j]);
                A.vIJ[j] = fmaf(a, cc, A.vIJ[j]);
            } else {
                A.vI[j] -= a; A.vJ[j] -= cc;
                A.vI2[j] = fmaf(-a, a, A.vI2[j]);
                A.vJ2[j] = fmaf(-cc, cc, A.vJ2[j]);
                A.vIJ[j] = fmaf(-a, cc, A.vIJ[j]);
            }
        }
    }
}

// horizontal sliding 9-sum + epilogue for one output row
__device__ __forceinline__ void hrow(const Acc& A, int lane, float& acc) {
    float LI[4], LJ[4], LI2[4], LJ2[4], LIJ[4];
    float RI[4], RJ[4], RI2[4], RJ2[4], RIJ[4];
#pragma unroll
    for (int q = 0; q < 4; q++) {
        LI[q]  = __shfl_up_sync(0xffffffffu, A.vI[12 + q], 1);
        LJ[q]  = __shfl_up_sync(0xffffffffu, A.vJ[12 + q], 1);
        LI2[q] = __shfl_up_sync(0xffffffffu, A.vI2[12 + q], 1);
        LJ2[q] = __shfl_up_sync(0xffffffffu, A.vJ2[12 + q], 1);
        LIJ[q] = __shfl_up_sync(0xffffffffu, A.vIJ[12 + q], 1);
        RI[q]  = __shfl_down_sync(0xffffffffu, A.vI[q], 1);
        RJ[q]  = __shfl_down_sync(0xffffffffu, A.vJ[q], 1);
        RI2[q] = __shfl_down_sync(0xffffffffu, A.vI2[q], 1);
        RJ2[q] = __shfl_down_sync(0xffffffffu, A.vJ2[q], 1);
        RIJ[q] = __shfl_down_sync(0xffffffffu, A.vIJ[q], 1);
        if (lane == 0)  { LI[q] = LJ[q] = LI2[q] = LJ2[q] = LIJ[q] = 0.0f; }
        if (lane == 31) { RI[q] = RJ[q] = RI2[q] = RJ2[q] = RIJ[q] = 0.0f; }
    }

    float hI = 0, hJ = 0, hI2 = 0, hJ2 = 0, hIJ = 0;
#pragma unroll
    for (int i = 0; i < 9; i++) {
        hI  += WW(A.vI,  LI,  RI,  i);
        hJ  += WW(A.vJ,  LJ,  RJ,  i);
        hI2 += WW(A.vI2, LI2, RI2, i);
        hJ2 += WW(A.vJ2, LJ2, RJ2, i);
        hIJ += WW(A.vIJ, LIJ, RIJ, i);
    }
    const float s = 1.0f / 81.0f;
#pragma unroll
    for (int k = 0; k < OUTC; k++) {
        if (k > 0) {
            hI  += WW(A.vI,  LI,  RI,  k + 8) - WW(A.vI,  LI,  RI,  k - 1);
            hJ  += WW(A.vJ,  LJ,  RJ,  k + 8) - WW(A.vJ,  LJ,  RJ,  k - 1);
            hI2 += WW(A.vI2, LI2, RI2, k + 8) - WW(A.vI2, LI2, RI2, k - 1);
            hJ2 += WW(A.vJ2, LJ2, RJ2, k + 8) - WW(A.vJ2, LJ2, RJ2, k - 1);
            hIJ += WW(A.vIJ, LIJ, RIJ, k + 8) - WW(A.vIJ, LIJ, RIJ, k - 1);
        }
        float t = hI * s;
        float u = hJ * s;
        float cross = fmaf(-t, hJ, hIJ);
        float varI  = fmaf(-t, hI, hI2);
        float varJ  = fmaf(-u, hJ, hJ2);
        float denom = fmaf(varI, varJ, 1e-5f);
        acc += __fdividef(cross * cross, denom);
    }
}

__global__ __launch_bounds__(WPB * 32, 3)
void ncc_main(const float* __restrict__ gI, const float* __restrict__ gJ,
              float* __restrict__ out) {
    const int warp = blockIdx.x * WPB + (threadIdx.x >> 5);
    const int lane = threadIdx.x & 31;

    const int b     = warp >> 6;
    const int strip = warp & (NSTRIPS - 1);
    const int r0 = strip * STRIP;
    const int col0 = lane * OUTC;

    const float* __restrict__ Ib = gI + (size_t)b * (IMG_H * IMG_W) + col0;
    const float* __restrict__ Jb = gJ + (size_t)b * (IMG_H * IMG_W) + col0;

    Acc A;
#pragma unroll
    for (int j = 0; j < OUTC; j++)
        { A.vI[j] = A.vJ[j] = A.vI2[j] = A.vJ2[j] = A.vIJ[j] = 0.0f; }

    const int rlow = (r0 - 4 > 0) ? (r0 - 4) : 0;

    // warm-up: rows [rlow, r0+4)
    for (int rr = rlow; rr < r0 + 4; rr++) {
        float4 bi[4], bj[4];
        load_rows(Ib + rr * IMG_W, Jb + rr * IMG_W, bi, bj);
        update<true>(A, bi, bj);
    }

    // phase bounds (uniform per warp)
    const int subStart = (r0 + 1 > 5) ? (r0 + 1) : 5;       // first r with sub
    const int addEnd   = (r0 + STRIP < 508) ? (r0 + STRIP) : 508; // last r with add (+1)

    float acc = 0.0f;
    int r = r0;

    // phase A: add-only (1 iter interior, up to 5 on first strip)
    for (; r < subStart && r < r0 + STRIP; r++) {
        float4 bi[4], bj[4];
        load_rows(Ib + (r + 4) * IMG_W, Jb + (r + 4) * IMG_W, bi, bj);
        update<true>(A, bi, bj);
        hrow(A, lane, acc);
    }

    // phase B: steady state, branchless, prefetched add-row
    if (r < addEnd) {
        float4 ai[4], aj[4];
        load_rows(Ib + (r + 4) * IMG_W, Jb + (r + 4) * IMG_W, ai, aj);
        for (; r < addEnd; r++) {
            // sub row (L2-resident): issue loads first, cover with add-update
            float4 si[4], sj[4];
            load_rows(Ib + (r - 5) * IMG_W, Jb + (r - 5) * IMG_W, si, sj);
            update<true>(A, ai, aj);
            update<false>(A, si, sj);
            // prefetch next add row (DRAM): flight covered by horizontal math
            if (r + 1 < addEnd)
                load_rows(Ib + (r + 5) * IMG_W, Jb + (r + 5) * IMG_W, ai, aj);
            hrow(A, lane, acc);
        }
    }

    // phase C: sub-only (last strip tail)
    for (; r < r0 + STRIP; r++) {
        float4 si[4], sj[4];
        load_rows(Ib + (r - 5) * IMG_W, Jb + (r - 5) * IMG_W, si, sj);
        update<false>(A, si, sj);
        hrow(A, lane, acc);
    }

    // deterministic warp reduction -> per-warp partial
#pragma unroll
    for (int o = 16; o > 0; o >>= 1)
        acc += __shfl_down_sync(0xffffffffu, acc, o);
    if (lane == 0)
        g_partials[warp] = acc;

    // fused final reduction: last finishing block sums all partials
    __shared__ bool is_last;
    __shared__ float sm[WPB * 32];
    __syncthreads();
    if (threadIdx.x == 0) {
        __threadfence();
        unsigned int done = atomicAdd(&g_counter, 1u);
        is_last = (done == (unsigned int)(NBLOCKS - 1));
    }
    __syncthreads();
    if (!is_last) return;

    __threadfence();
    float v = 0.0f;
    for (int i = threadIdx.x; i < NTASK; i += WPB * 32)
        v += g_partials[i];
    sm[threadIdx.x] = v;
    __syncthreads();
#pragma unroll
    for (int stride = WPB * 16; stride > 0; stride >>= 1) {
        if (threadIdx.x < stride) sm[threadIdx.x] += sm[threadIdx.x + stride];
        __syncthreads();
    }
    if (threadIdx.x == 0) {
        out[0] = -sm[0] * (1.0f / (float)(NBATCH * IMG_H * IMG_W));
        g_counter = 0;
    }
}

extern "C" void kernel_launch(void* const* d_in, const int* in_sizes, int n_in,
                              void* d_out, int out_size) {
    const float* y_true = (const float*)d_in[0];
    const float* y_pred = (const float*)d_in[1];
    float* out = (float*)d_out;
    (void)in_sizes; (void)n_in; (void)out_size;

    ncc_main<<<NBLOCKS, WPB * 32>>>(y_true, y_pred, out);
}

// round 8
// speedup vs baseline: 1.1056x; 1.1056x over previous
#include <cuda_runtime.h>

// NCC2D: local normalized cross-correlation, 9x9 box, zero pad, scalar -mean(cc)
// Inputs: y_true, y_pred : [32,1,512,512] fp32. Output: 1 fp32.
//
// cross = IJ_sum - I_sum*J_sum/81 ; I_var = I2_sum - I_sum^2/81 (ditto J)
// cc = cross^2 / (I_var*J_var + 1e-5) ; out = -mean(cc)
//
// R4 structure (warp spans full 512-col row, 16 cols/lane, shuffle halos)
// + f32x2 packed vertical sliding updates (sm_103a packed FMA pipe).

#define IMG_W 512
#define IMG_H 512
#define NBATCH 32
#define STRIP 8
#define NSTRIPS (IMG_H / STRIP)      // 64
#define NTASK (NBATCH * NSTRIPS)     // 2048 warps
#define WPB 4
#define NBLOCKS (NTASK / WPB)        // 512
#define OUTC 16
#define NPAIR (OUTC / 2)             // 8 packed column-pairs per lane

__device__ float g_partials[NTASK];
__device__ unsigned int g_counter;

typedef unsigned long long u64;

__device__ __forceinline__ u64 pack2(float lo, float hi) {
    u64 r; asm("mov.b64 %0, {%1, %2};" : "=l"(r) : "f"(lo), "f"(hi)); return r;
}
__device__ __forceinline__ void unpack2(u64 p, float& lo, float& hi) {
    asm("mov.b64 {%0, %1}, %2;" : "=f"(lo), "=f"(hi) : "l"(p));
}
__device__ __forceinline__ u64 add2(u64 a, u64 b) {
    u64 d; asm("add.rn.f32x2 %0, %1, %2;" : "=l"(d) : "l"(a), "l"(b)); return d;
}
__device__ __forceinline__ u64 mul2(u64 a, u64 b) {
    u64 d; asm("mul.rn.f32x2 %0, %1, %2;" : "=l"(d) : "l"(a), "l"(b)); return d;
}
__device__ __forceinline__ u64 fma2(u64 a, u64 b, u64 c) {
    u64 d; asm("fma.rn.f32x2 %0, %1, %2, %3;" : "=l"(d) : "l"(a), "l"(b), "l"(c)); return d;
}

#define WW(A, L, R, i) ((i) < 4 ? (L)[(i)] : ((i) < 20 ? (A)[(i)-4] : (R)[(i)-20]))

struct Acc {  // packed: pair p holds columns 2p, 2p+1
    u64 vI[NPAIR], vJ[NPAIR], vI2[NPAIR], vJ2[NPAIR], vIJ[NPAIR];
};

// load one row's 16 cols of I and J as 8 packed pairs each
__device__ __forceinline__ void load_rows(const float* __restrict__ Irow,
                                          const float* __restrict__ Jrow,
                                          u64 (&ai)[NPAIR], u64 (&aj)[NPAIR]) {
    const float4* pI = reinterpret_cast<const float4*>(Irow);
    const float4* pJ = reinterpret_cast<const float4*>(Jrow);
#pragma unroll
    for (int c = 0; c < 4; c++) {
        float4 fi = pI[c], fj = pJ[c];
        ai[2*c]   = pack2(fi.x, fi.y);
        ai[2*c+1] = pack2(fi.z, fi.w);
        aj[2*c]   = pack2(fj.x, fj.y);
        aj[2*c+1] = pack2(fj.z, fj.w);
    }
}

__device__ __forceinline__ void update_add(Acc& A, const u64 (&ai)[NPAIR],
                                           const u64 (&aj)[NPAIR]) {
#pragma unroll
    for (int p = 0; p < NPAIR; p++) {
        u64 a = ai[p], c = aj[p];
        A.vI[p]  = add2(A.vI[p], a);
        A.vJ[p]  = add2(A.vJ[p], c);
        A.vI2[p] = fma2(a, a, A.vI2[p]);
        A.vJ2[p] = fma2(c, c, A.vJ2[p]);
        A.vIJ[p] = fma2(a, c, A.vIJ[p]);
    }
}

__device__ __forceinline__ void update_sub(Acc& A, const u64 (&ai)[NPAIR],
                                           const u64 (&aj)[NPAIR], u64 NM1) {
#pragma unroll
    for (int p = 0; p < NPAIR; p++) {
        u64 a = ai[p], c = aj[p];
        A.vI[p]  = fma2(a, NM1, A.vI[p]);            // v -= a
        A.vJ[p]  = fma2(c, NM1, A.vJ[p]);
        A.vI2[p] = fma2(mul2(a, a), NM1, A.vI2[p]);  // v -= a*a
        A.vJ2[p] = fma2(mul2(c, c), NM1, A.vJ2[p]);
        A.vIJ[p] = fma2(mul2(a, c), NM1, A.vIJ[p]);
    }
}

// horizontal sliding 9-sum + epilogue for one output row
__device__ __forceinline__ void hrow(const Acc& A, int lane, float& acc) {
    // unpack accumulators (register-pair aliasing; no real moves expected)
    float vI[OUTC], vJ[OUTC], vI2[OUTC], vJ2[OUTC], vIJ[OUTC];
#pragma unroll
    for (int p = 0; p < NPAIR; p++) {
        unpack2(A.vI[p],  vI[2*p],  vI[2*p+1]);
        unpack2(A.vJ[p],  vJ[2*p],  vJ[2*p+1]);
        unpack2(A.vI2[p], vI2[2*p], vI2[2*p+1]);
        unpack2(A.vJ2[p], vJ2[2*p], vJ2[2*p+1]);
        unpack2(A.vIJ[p], vIJ[2*p], vIJ[2*p+1]);
    }

    float LI[4], LJ[4], LI2[4], LJ2[4], LIJ[4];
    float RI[4], RJ[4], RI2[4], RJ2[4], RIJ[4];
#pragma unroll
    for (int q = 0; q < 4; q++) {
        LI[q]  = __shfl_up_sync(0xffffffffu, vI[12 + q], 1);
        LJ[q]  = __shfl_up_sync(0xffffffffu, vJ[12 + q], 1);
        LI2[q] = __shfl_up_sync(0xffffffffu, vI2[12 + q], 1);
        LJ2[q] = __shfl_up_sync(0xffffffffu, vJ2[12 + q], 1);
        LIJ[q] = __shfl_up_sync(0xffffffffu, vIJ[12 + q], 1);
        RI[q]  = __shfl_down_sync(0xffffffffu, vI[q], 1);
        RJ[q]  = __shfl_down_sync(0xffffffffu, vJ[q], 1);
        RI2[q] = __shfl_down_sync(0xffffffffu, vI2[q], 1);
        RJ2[q] = __shfl_down_sync(0xffffffffu, vJ2[q], 1);
        RIJ[q] = __shfl_down_sync(0xffffffffu, vIJ[q], 1);
        if (lane == 0)  { LI[q] = LJ[q] = LI2[q] = LJ2[q] = LIJ[q] = 0.0f; }
        if (lane == 31) { RI[q] = RJ[q] = RI2[q] = RJ2[q] = RIJ[q] = 0.0f; }
    }

    float hI = 0, hJ = 0, hI2 = 0, hJ2 = 0, hIJ = 0;
#pragma unroll
    for (int i = 0; i < 9; i++) {
        hI  += WW(vI,  LI,  RI,  i);
        hJ  += WW(vJ,  LJ,  RJ,  i);
        hI2 += WW(vI2, LI2, RI2, i);
        hJ2 += WW(vJ2, LJ2, RJ2, i);
        hIJ += WW(vIJ, LIJ, RIJ, i);
    }
    const float s = 1.0f / 81.0f;
#pragma unroll
    for (int k = 0; k < OUTC; k++) {
        if (k > 0) {
            hI  += WW(vI,  LI,  RI,  k + 8) - WW(vI,  LI,  RI,  k - 1);
            hJ  += WW(vJ,  LJ,  RJ,  k + 8) - WW(vJ,  LJ,  RJ,  k - 1);
            hI2 += WW(vI2, LI2, RI2, k + 8) - WW(vI2, LI2, RI2, k - 1);
            hJ2 += WW(vJ2, LJ2, RJ2, k + 8) - WW(vJ2, LJ2, RJ2, k - 1);
            hIJ += WW(vIJ, LIJ, RIJ, k + 8) - WW(vIJ, LIJ, RIJ, k - 1);
        }
        float t = hI * s;
        float u = hJ * s;
        float cross = fmaf(-t, hJ, hIJ);
        float varI  = fmaf(-t, hI, hI2);
        float varJ  = fmaf(-u, hJ, hJ2);
        float denom = fmaf(varI, varJ, 1e-5f);
        acc += __fdividef(cross * cross, denom);
    }
}

__global__ __launch_bounds__(WPB * 32, 4)
void ncc_main(const float* __restrict__ gI, const float* __restrict__ gJ,
              float* __restrict__ out) {
    const int warp = blockIdx.x * WPB + (threadIdx.x >> 5);
    const int lane = threadIdx.x & 31;

    const int b     = warp >> 6;
    const int strip = warp & (NSTRIPS - 1);
    const int r0 = strip * STRIP;
    const int col0 = lane * OUTC;

    const float* __restrict__ Ib = gI + (size_t)b * (IMG_H * IMG_W) + col0;
    const float* __restrict__ Jb = gJ + (size_t)b * (IMG_H * IMG_W) + col0;

    const u64 NM1 = pack2(-1.0f, -1.0f);

    Acc A;
#pragma unroll
    for (int p = 0; p < NPAIR; p++)
        { A.vI[p] = A.vJ[p] = A.vI2[p] = A.vJ2[p] = A.vIJ[p] = 0ull; }

    const int rlow = (r0 - 4 > 0) ? (r0 - 4) : 0;

    // warm-up: rows [rlow, r0+4)
    for (int rr = rlow; rr < r0 + 4; rr++) {
        u64 ai[NPAIR], aj[NPAIR];
        load_rows(Ib + rr * IMG_W, Jb + rr * IMG_W, ai, aj);
        update_add(A, ai, aj);
    }

    float acc = 0.0f;

    for (int r = r0; r < r0 + STRIP; r++) {
        const int rin = r + 4;
        if (rin < IMG_H) {
            u64 ai[NPAIR], aj[NPAIR];
            load_rows(Ib + rin * IMG_W, Jb + rin * IMG_W, ai, aj);
            update_add(A, ai, aj);
        }
        const int rout = r - 5;
        if (rout >= rlow) {
            u64 ai[NPAIR], aj[NPAIR];
            load_rows(Ib + rout * IMG_W, Jb + rout * IMG_W, ai, aj);
            update_sub(A, ai, aj, NM1);
        }
        hrow(A, lane, acc);
    }

    // deterministic warp reduction -> per-warp partial
#pragma unroll
    for (int o = 16; o > 0; o >>= 1)
        acc += __shfl_down_sync(0xffffffffu, acc, o);
    if (lane == 0)
        g_partials[warp] = acc;

    // fused final reduction: last finishing block sums all partials
    __shared__ bool is_last;
    __shared__ float sm[WPB * 32];
    __syncthreads();
    if (threadIdx.x == 0) {
        __threadfence();
        unsigned int done = atomicAdd(&g_counter, 1u);
        is_last = (done == (unsigned int)(NBLOCKS - 1));
    }
    __syncthreads();
    if (!is_last) return;

    __threadfence();
    float v = 0.0f;
    for (int i = threadIdx.x; i < NTASK; i += WPB * 32)
        v += g_partials[i];
    sm[threadIdx.x] = v;
    __syncthreads();
#pragma unroll
    for (int stride = WPB * 16; stride > 0; stride >>= 1) {
        if (threadIdx.x < stride) sm[threadIdx.x] += sm[threadIdx.x + stride];
        __syncthreads();
    }
    if (threadIdx.x == 0) {
        out[0] = -sm[0] * (1.0f / (float)(NBATCH * IMG_H * IMG_W));
        g_counter = 0;
    }
}

extern "C" void kernel_launch(void* const* d_in, const int* in_sizes, int n_in,
                              void* d_out, int out_size) {
    const float* y_true = (const float*)d_in[0];
    const float* y_pred = (const float*)d_in[1];
    float* out = (float*)d_out;
    (void)in_sizes; (void)n_in; (void)out_size;

    ncc_main<<<NBLOCKS, WPB * 32>>>(y_true, y_pred, out);
}